// round 5
// baseline (speedup 1.0000x reference)
#include <cuda_runtime.h>
#include <math_constants.h>

// SoftmaxTreeWithLoss on GB300.
// x: [N=16, C=4096, H=26, W=26] f32; label: [N,26,26] i32 in [0,C)
// Tree: group 0 = channels [0,512) (roots), then 512 groups of 7 children.
// Loss = -sum over positions of ( logp(label | its group) + logp(parent | root group) ) / N
// Only group 0's LSE (512 ch) + one 7-wide child group per position are needed
// => ~22.4 MB of traffic instead of 177 MB. Pure HBM-bound streaming reduction.

#define HW_SZ 676              // 26*26
#define CN 4096
#define ROOT_CH 512
#define POS_PER_BLOCK 32
#define NWARPS 8
#define CH_PER_WARP 64         // 512 / 8

__global__ __launch_bounds__(256, 2)
void tree_loss_kernel(const float* __restrict__ x,
                      const int*   __restrict__ label,
                      const int*   __restrict__ group_offsets,
                      const int*   __restrict__ group_sizes,
                      const int*   __restrict__ cid_groups,
                      const int*   __restrict__ parents,
                      float* __restrict__ out,
                      int M, float inv_norm)
{
    __shared__ float sm_m[NWARPS][POS_PER_BLOCK];
    __shared__ float sm_s[NWARPS][POS_PER_BLOCK];

    const int lane = threadIdx.x & 31;
    const int w    = threadIdx.x >> 5;
    const int pos  = blockIdx.x * POS_PER_BLOCK + lane;
    const bool valid = pos < M;

    const int n  = valid ? (pos / HW_SZ) : 0;
    const int hw = valid ? (pos - n * HW_SZ) : 0;
    const float* base = x + (size_t)n * CN * HW_SZ + hw;

    // ---- each warp scans 64 of the 512 root channels for its 32 positions ----
    // Fully unrolled loads: high MLP, each LDG is one coalesced 128B wavefront.
    float v[CH_PER_WARP];
    const int c0 = w * CH_PER_WARP;
    if (valid) {
        #pragma unroll
        for (int j = 0; j < CH_PER_WARP; j++)
            v[j] = base[(size_t)(c0 + j) * HW_SZ];
    } else {
        #pragma unroll
        for (int j = 0; j < CH_PER_WARP; j++)
            v[j] = -CUDART_INF_F;
    }

    float m = -CUDART_INF_F;
    #pragma unroll
    for (int j = 0; j < CH_PER_WARP; j++) m = fmaxf(m, v[j]);
    float s = 0.f;
    #pragma unroll
    for (int j = 0; j < CH_PER_WARP; j++) s += __expf(v[j] - m);

    sm_m[w][lane] = m;
    sm_s[w][lane] = s;
    __syncthreads();

    // ---- warp 0: merge the 8 partial (max,sum) pairs, then walk the chain ----
    if (w == 0) {
        float M0 = sm_m[0][lane], S0 = sm_s[0][lane];
        #pragma unroll
        for (int q = 1; q < NWARPS; q++) {
            float mq = sm_m[q][lane], sq = sm_s[q][lane];
            float Mn = fmaxf(M0, mq);
            S0 = S0 * __expf(M0 - Mn) + sq * __expf(mq - Mn);
            M0 = Mn;
        }
        const float lse0 = M0 + __logf(S0);   // root-group log-sum-exp

        float loss = 0.f;
        if (valid) {
            int cur = label[pos];
            #pragma unroll 1
            for (int d = 0; d < 8; d++) {
                if (cur < 0) break;
                const int g = cid_groups[cur];
                float lp;
                if (g == 0) {
                    // root group: reload the single logit (L2 hit), use block LSE
                    lp = base[(size_t)cur * HW_SZ] - lse0;
                } else {
                    const int go = group_offsets[g];
                    const int gs = group_sizes[g];     // 7
                    float vv[8];
                    float mm = -CUDART_INF_F;
                    float xv = 0.f;
                    for (int j = 0; j < gs; j++) {
                        vv[j] = base[(size_t)(go + j) * HW_SZ];
                        if (go + j == cur) xv = vv[j];
                        mm = fmaxf(mm, vv[j]);
                    }
                    float ss = 0.f;
                    for (int j = 0; j < gs; j++) ss += __expf(vv[j] - mm);
                    lp = xv - mm - __logf(ss);
                }
                loss -= lp;
                cur = parents[cur];
            }
        }

        // warp-sum over the 32 positions, one atomic per block
        #pragma unroll
        for (int o = 16; o; o >>= 1)
            loss += __shfl_xor_sync(0xffffffffu, loss, o);
        if (lane == 0)
            atomicAdd(out, loss * inv_norm);
    }
}

extern "C" void kernel_launch(void* const* d_in, const int* in_sizes, int n_in,
                              void* d_out, int out_size)
{
    const float* x     = (const float*)d_in[0];
    const int* label   = (const int*)d_in[1];
    const int* g_off   = (const int*)d_in[2];
    const int* g_sz    = (const int*)d_in[3];
    const int* cid     = (const int*)d_in[4];
    const int* par     = (const int*)d_in[5];
    float* out         = (float*)d_out;

    const int M = in_sizes[1];          // N*H*W (label element count)
    const int N = M / HW_SZ;            // batch size for normalization
    const float inv_norm = 1.0f / (float)N;

    cudaMemsetAsync(d_out, 0, sizeof(float));

    const int blocks = (M + POS_PER_BLOCK - 1) / POS_PER_BLOCK;
    tree_loss_kernel<<<blocks, 256>>>(x, label, g_off, g_sz, cid, par,
                                      out, M, inv_norm);
}